// round 1
// baseline (speedup 1.0000x reference)
#include <cuda_runtime.h>
#include <stdint.h>

#define BB 256
#define LL 8192
#define EE 64
#define THRV 1.5f
#define M3 2731            // ceil(L/3) chain nodes
#define CHUNKS 64
#define CH 43              // 64*43 = 2752 >= 2731
#define PT 11              // scan groups per thread: 256*11 = 2816 >= 2731

__global__ __launch_bounds__(256, 2)
void patcher_kernel(const int* __restrict__ x,
                    const float* __restrict__ w1,
                    const float* __restrict__ b1,
                    const float* __restrict__ w2,
                    const float* __restrict__ b2,
                    float* __restrict__ out_feat,   // [B,E]
                    float* __restrict__ out_ent)    // [B,L]
{
    __shared__ uint8_t  xs[LL];
    __shared__ uint8_t  bits[M3 + 8];
    __shared__ int      packed[M3];      // (cs3 << 1) | bit
    __shared__ float    means[M3];
    __shared__ float    clog[16];        // c * log2(c)
    __shared__ float    ltab[16];        // log2(t)
    __shared__ float    itab[16];        // 1/t
    __shared__ int      warp_sums[8];
    __shared__ uint8_t  exit_off[CHUNKS][4];
    __shared__ uint16_t cntt[CHUNKS][4];
    __shared__ uint16_t base_c[CHUNKS];
    __shared__ uint8_t  entry_c[CHUNKS];
    __shared__ int      total_s;
    __shared__ int      np_s;
    __shared__ float    hpart[4 * EE];
    __shared__ float    havg[EE];

    const int b = blockIdx.x;
    const int t = threadIdx.x;
    const int lane = t & 31;
    const int wid  = t >> 5;
    const int* __restrict__ xrow = x + (long)b * LL;

    // ---- tables ----
    if (t < 16) {
        float ft = (float)t;
        clog[t] = (t >= 2) ? ft * log2f(ft) : 0.0f;
        ltab[t] = (t >= 1) ? log2f(ft) : 0.0f;
        itab[t] = (t >= 1) ? 1.0f / ft : 0.0f;
    }

    // ---- load x row into shared as bytes (coalesced int4 loads) ----
    {
        const int4* xv = (const int4*)xrow;
        uchar4* xb = (uchar4*)xs;
        for (int idx = t; idx < LL / 4; idx += 256) {
            int4 v = xv[idx];
            uchar4 u;
            u.x = (uint8_t)v.x; u.y = (uint8_t)v.y;
            u.z = (uint8_t)v.z; u.w = (uint8_t)v.w;
            xb[idx] = u;
        }
    }
    __syncthreads();

    // ---- entropy: each thread handles 32 consecutive positions ----
    {
        const int i0 = t * 32;
        // 5-class histogram packed into bytes of a u64
        unsigned long long cp = 0ull;
        int lo = i0 - 4; if (lo < 0) lo = 0;
        int hi = i0 + 4; if (hi > LL - 1) hi = LL - 1;
        for (int j = lo; j <= hi; j++) cp += 1ull << (8 * xs[j]);

        int r3 = i0 % 3;
        float ebuf[4];
        float* erow = out_ent + (long)b * LL + i0;
        #pragma unroll 4
        for (int k = 0; k < 32; k++) {
            int i = i0 + k;
            int wlo = i - 4; if (wlo < 0) wlo = 0;
            int whi = i + 4; if (whi > LL - 1) whi = LL - 1;
            int tot = whi - wlo + 1;
            float S = clog[cp & 0xFF] + clog[(cp >> 8) & 0xFF]
                    + clog[(cp >> 16) & 0xFF] + clog[(cp >> 24) & 0xFF]
                    + clog[(cp >> 32) & 0xFF];
            float ent = ltab[tot] - S * itab[tot];
            ebuf[k & 3] = ent;
            if ((k & 3) == 3) {
                *((float4*)(erow + (k - 3))) = *((float4*)ebuf);
            }
            if (r3 == 0) bits[i / 3] = (ent > THRV) ? 1 : 0;
            r3 = (r3 == 2) ? 0 : r3 + 1;
            // slide window: drop i-4, add i+5
            if (i - 4 >= 0) cp -= 1ull << (8 * xs[i - 4]);
            if (i + 5 < LL) cp += 1ull << (8 * xs[i + 5]);
        }
    }
    __syncthreads();

    // ---- 3-group sums + block exclusive scan; pack (cs3<<1)|bit ----
    {
        const int m0 = t * PT;
        int lpre[PT];
        int s = 0;
        #pragma unroll
        for (int q = 0; q < PT; q++) {
            int m = m0 + q;
            int v = 0;
            if (m < M3) {
                int i = 3 * m;
                v = xs[i];
                if (i + 1 < LL) v += xs[i + 1];
                if (i + 2 < LL) v += xs[i + 2];
            }
            lpre[q] = s;
            s += v;
        }
        // warp inclusive scan of per-thread totals
        int v = s;
        #pragma unroll
        for (int d = 1; d < 32; d <<= 1) {
            int n = __shfl_up_sync(0xffffffffu, v, d);
            if (lane >= d) v += n;
        }
        if (lane == 31) warp_sums[wid] = v;
        int excl_in_warp = v - s;
        __syncthreads();
        if (wid == 0) {
            int orig = (lane < 8) ? warp_sums[lane] : 0;
            int wv = orig;
            #pragma unroll
            for (int d = 1; d < 8; d <<= 1) {
                int n = __shfl_up_sync(0xffffffffu, wv, d);
                if (lane >= d) wv += n;
            }
            if (lane < 8) warp_sums[lane] = wv - orig;  // exclusive
            if (lane == 7) total_s = wv;                // full row sum
        }
        __syncthreads();
        int base = warp_sums[wid] + excl_in_warp;
        #pragma unroll
        for (int q = 0; q < PT; q++) {
            int m = m0 + q;
            if (m < M3) packed[m] = ((base + lpre[q]) << 1) | bits[m];
        }
    }
    __syncthreads();

    // ---- chain walk, phase A: all (chunk, entry-offset) candidates ----
    {
        int c = t >> 2, r = t & 3;
        int mend = (c + 1) * CH; if (mend > M3) mend = M3;
        int m = c * CH + r;
        int count = 0;
        while (m < mend) {
            int bit = packed[m] & 1;
            m += bit ? 1 : 4;
            count++;
        }
        exit_off[c][r] = (uint8_t)(m - mend);
        cntt[c][r] = (uint16_t)count;
    }
    __syncthreads();

    // ---- serial stitch across 64 chunks (thread 0) ----
    if (t == 0) {
        int off = 0, np = 0;
        #pragma unroll 4
        for (int c = 0; c < CHUNKS; c++) {
            entry_c[c] = (uint8_t)off;
            base_c[c]  = (uint16_t)np;
            np += cntt[c][off];
            off = exit_off[c][off];
        }
        np_s = np;
    }
    __syncthreads();

    // ---- chain walk, phase B: emit patch means (64 threads) ----
    if (t < CHUNKS) {
        int c = t;
        int mend = (c + 1) * CH; if (mend > M3) mend = M3;
        int m = c * CH + entry_c[c];
        int p = base_c[c];
        int total = total_s;
        while (m < mend) {
            int pk  = packed[m];
            int bit = pk & 1;
            int cs  = pk >> 1;
            int s   = bit ? 1 : 4;
            float mean;
            if (m + s <= 2730) {            // j = 3(m+s) <= 8190 < L
                int cs2 = packed[m + s] >> 1;
                mean = (float)(cs2 - cs) * (bit ? (1.0f / 3.0f) : (1.0f / 12.0f));
            } else {                        // clipped final patch: j = L
                int i = 3 * m;
                mean = (float)(total - cs) / (float)(LL - i);
            }
            means[p++] = mean;
            m += s;
        }
    }
    __syncthreads();

    // ---- per-patch relu accumulate: e = t&63, 4 patch groups ----
    {
        int e = t & 63;
        int g = t >> 6;
        float w1e = w1[e];
        float b1e = b1[e];
        int np = np_s;
        float acc = 0.0f;
        for (int p = g; p < np; p += 4) {
            float mv = means[p];
            acc += fmaxf(fmaf(mv, w1e, b1e), 0.0f);
        }
        hpart[g * EE + e] = acc;
    }
    __syncthreads();
    if (t < EE) {
        float inv = 1.0f / (float)np_s;
        havg[t] = (hpart[t] + hpart[EE + t] + hpart[2 * EE + t] + hpart[3 * EE + t]) * inv;
    }
    __syncthreads();

    // ---- final 64x64 GEMV: feat_e = b2[e] + sum_k havg[k]*w2[e,k] ----
    if (t < EE) {
        const float* __restrict__ w2r = w2 + t * EE;
        float f = b2[t];
        #pragma unroll 8
        for (int k = 0; k < EE; k++) f = fmaf(havg[k], w2r[k], f);
        out_feat[(long)b * EE + t] = f;
    }
}

extern "C" void kernel_launch(void* const* d_in, const int* in_sizes, int n_in,
                              void* d_out, int out_size) {
    const int*   x  = (const int*)d_in[0];
    const float* w1 = (const float*)d_in[1];
    const float* b1 = (const float*)d_in[2];
    const float* w2 = (const float*)d_in[3];
    const float* b2 = (const float*)d_in[4];
    float* out = (float*)d_out;
    patcher_kernel<<<BB, 256>>>(x, w1, b1, w2, b2, out, out + BB * EE);
}

// round 2
// speedup vs baseline: 1.0095x; 1.0095x over previous
#include <cuda_runtime.h>
#include <stdint.h>

#define BB 256
#define LL 8192
#define EE 64
#define THRV 1.5f
#define M3 2731            // ceil(L/3) chain nodes
#define CHUNKS 64
#define CH 43              // 64*43 = 2752 >= 2731
#define PT 11              // scan groups per thread: 256*11 = 2816 >= 2731

__global__ __launch_bounds__(256, 2)
void patcher_kernel(const int* __restrict__ x,
                    const float* __restrict__ w1,
                    const float* __restrict__ b1,
                    const float* __restrict__ w2,
                    const float* __restrict__ b2,
                    float* __restrict__ out_feat,   // [B,E]
                    float* __restrict__ out_ent)    // [B,L]
{
    __shared__ uint8_t  xs[LL];
    __shared__ uint8_t  bits[M3 + 8];
    __shared__ int      packed[M3];      // (cs3 << 1) | bit
    __shared__ float    means[M3];
    __shared__ float    clog[16];        // c * log2(c)
    __shared__ float    ltab[16];        // log2(t)
    __shared__ float    itab[16];        // 1/t
    __shared__ int      warp_sums[8];
    __shared__ uint8_t  exit_off[CHUNKS][4];
    __shared__ uint16_t cntt[CHUNKS][4];
    __shared__ uint16_t base_c[CHUNKS];
    __shared__ uint8_t  entry_c[CHUNKS];
    __shared__ int      total_s;
    __shared__ int      np_s;
    __shared__ float    hpart[4 * EE];
    __shared__ float    havg[EE];

    const int b = blockIdx.x;
    const int t = threadIdx.x;
    const int lane = t & 31;
    const int wid  = t >> 5;
    const int* __restrict__ xrow = x + (long)b * LL;

    // ---- tables ----
    if (t < 16) {
        float ft = (float)t;
        clog[t] = (t >= 2) ? ft * log2f(ft) : 0.0f;
        ltab[t] = (t >= 1) ? log2f(ft) : 0.0f;
        itab[t] = (t >= 1) ? 1.0f / ft : 0.0f;
    }

    // ---- load x row into shared as bytes (coalesced int4 loads) ----
    {
        const int4* xv = (const int4*)xrow;
        uchar4* xb = (uchar4*)xs;
        for (int idx = t; idx < LL / 4; idx += 256) {
            int4 v = xv[idx];
            uchar4 u;
            u.x = (uint8_t)v.x; u.y = (uint8_t)v.y;
            u.z = (uint8_t)v.z; u.w = (uint8_t)v.w;
            xb[idx] = u;
        }
    }
    __syncthreads();

    // ---- entropy: each thread handles 32 consecutive positions ----
    {
        const int i0 = t * 32;
        // 5-class histogram packed into bytes of a u64
        unsigned long long cp = 0ull;
        int lo = i0 - 4; if (lo < 0) lo = 0;
        int hi = i0 + 4; if (hi > LL - 1) hi = LL - 1;
        for (int j = lo; j <= hi; j++) cp += 1ull << (8 * xs[j]);

        int r3 = i0 % 3;
        float ebuf[4];
        float* erow = out_ent + (long)b * LL + i0;
        #pragma unroll 4
        for (int k = 0; k < 32; k++) {
            int i = i0 + k;
            int wlo = i - 4; if (wlo < 0) wlo = 0;
            int whi = i + 4; if (whi > LL - 1) whi = LL - 1;
            int tot = whi - wlo + 1;
            float S = clog[cp & 0xFF] + clog[(cp >> 8) & 0xFF]
                    + clog[(cp >> 16) & 0xFF] + clog[(cp >> 24) & 0xFF]
                    + clog[(cp >> 32) & 0xFF];
            float ent = ltab[tot] - S * itab[tot];
            ebuf[k & 3] = ent;
            if ((k & 3) == 3) {
                *((float4*)(erow + (k - 3))) = *((float4*)ebuf);
            }
            if (r3 == 0) bits[i / 3] = (ent > THRV) ? 1 : 0;
            r3 = (r3 == 2) ? 0 : r3 + 1;
            // slide window: drop i-4, add i+5
            if (i - 4 >= 0) cp -= 1ull << (8 * xs[i - 4]);
            if (i + 5 < LL) cp += 1ull << (8 * xs[i + 5]);
        }
    }
    __syncthreads();

    // ---- 3-group sums + block exclusive scan; pack (cs3<<1)|bit ----
    {
        const int m0 = t * PT;
        int lpre[PT];
        int s = 0;
        #pragma unroll
        for (int q = 0; q < PT; q++) {
            int m = m0 + q;
            int v = 0;
            if (m < M3) {
                int i = 3 * m;
                v = xs[i];
                if (i + 1 < LL) v += xs[i + 1];
                if (i + 2 < LL) v += xs[i + 2];
            }
            lpre[q] = s;
            s += v;
        }
        // warp inclusive scan of per-thread totals
        int v = s;
        #pragma unroll
        for (int d = 1; d < 32; d <<= 1) {
            int n = __shfl_up_sync(0xffffffffu, v, d);
            if (lane >= d) v += n;
        }
        if (lane == 31) warp_sums[wid] = v;
        int excl_in_warp = v - s;
        __syncthreads();
        if (wid == 0) {
            int orig = (lane < 8) ? warp_sums[lane] : 0;
            int wv = orig;
            #pragma unroll
            for (int d = 1; d < 8; d <<= 1) {
                int n = __shfl_up_sync(0xffffffffu, wv, d);
                if (lane >= d) wv += n;
            }
            if (lane < 8) warp_sums[lane] = wv - orig;  // exclusive
            if (lane == 7) total_s = wv;                // full row sum
        }
        __syncthreads();
        int base = warp_sums[wid] + excl_in_warp;
        #pragma unroll
        for (int q = 0; q < PT; q++) {
            int m = m0 + q;
            if (m < M3) packed[m] = ((base + lpre[q]) << 1) | bits[m];
        }
    }
    __syncthreads();

    // ---- chain walk, phase A: all (chunk, entry-offset) candidates ----
    {
        int c = t >> 2, r = t & 3;
        int mend = (c + 1) * CH; if (mend > M3) mend = M3;
        int m = c * CH + r;
        int count = 0;
        while (m < mend) {
            int bit = packed[m] & 1;
            m += bit ? 1 : 4;
            count++;
        }
        exit_off[c][r] = (uint8_t)(m - mend);
        cntt[c][r] = (uint16_t)count;
    }
    __syncthreads();

    // ---- serial stitch across 64 chunks (thread 0) ----
    if (t == 0) {
        int off = 0, np = 0;
        #pragma unroll 4
        for (int c = 0; c < CHUNKS; c++) {
            entry_c[c] = (uint8_t)off;
            base_c[c]  = (uint16_t)np;
            np += cntt[c][off];
            off = exit_off[c][off];
        }
        np_s = np;
    }
    __syncthreads();

    // ---- chain walk, phase B: emit patch means (64 threads) ----
    if (t < CHUNKS) {
        int c = t;
        int mend = (c + 1) * CH; if (mend > M3) mend = M3;
        int m = c * CH + entry_c[c];
        int p = base_c[c];
        int total = total_s;
        while (m < mend) {
            int pk  = packed[m];
            int bit = pk & 1;
            int cs  = pk >> 1;
            int s   = bit ? 1 : 4;
            float mean;
            if (m + s <= 2730) {            // j = 3(m+s) <= 8190 < L
                int cs2 = packed[m + s] >> 1;
                mean = (float)(cs2 - cs) * (bit ? (1.0f / 3.0f) : (1.0f / 12.0f));
            } else {                        // clipped final patch: j = L
                int i = 3 * m;
                mean = (float)(total - cs) / (float)(LL - i);
            }
            means[p++] = mean;
            m += s;
        }
    }
    __syncthreads();

    // ---- per-patch relu accumulate: e = t&63, 4 patch groups ----
    {
        int e = t & 63;
        int g = t >> 6;
        float w1e = w1[e];
        float b1e = b1[e];
        int np = np_s;
        float acc = 0.0f;
        for (int p = g; p < np; p += 4) {
            float mv = means[p];
            acc += fmaxf(fmaf(mv, w1e, b1e), 0.0f);
        }
        hpart[g * EE + e] = acc;
    }
    __syncthreads();
    if (t < EE) {
        float inv = 1.0f / (float)np_s;
        havg[t] = (hpart[t] + hpart[EE + t] + hpart[2 * EE + t] + hpart[3 * EE + t]) * inv;
    }
    __syncthreads();

    // ---- final 64x64 GEMV: feat_e = b2[e] + sum_k havg[k]*w2[e,k] ----
    if (t < EE) {
        const float* __restrict__ w2r = w2 + t * EE;
        float f = b2[t];
        #pragma unroll 8
        for (int k = 0; k < EE; k++) f = fmaf(havg[k], w2r[k], f);
        out_feat[(long)b * EE + t] = f;
    }
}

extern "C" void kernel_launch(void* const* d_in, const int* in_sizes, int n_in,
                              void* d_out, int out_size) {
    const int*   x  = (const int*)d_in[0];
    const float* w1 = (const float*)d_in[1];
    const float* b1 = (const float*)d_in[2];
    const float* w2 = (const float*)d_in[3];
    const float* b2 = (const float*)d_in[4];
    float* out = (float*)d_out;
    patcher_kernel<<<BB, 256>>>(x, w1, b1, w2, b2, out, out + BB * EE);
}

// round 3
// speedup vs baseline: 1.7805x; 1.7637x over previous
#include <cuda_runtime.h>
#include <stdint.h>

#define BB 256
#define LL 8192
#define EE 64
#define M3 2731            // ceil(L/3) chain nodes (patch starts are multiples of 3)
#define CH 11              // m-nodes per chunk, 256 chunks: 256*11 = 2816 >= 2731
#define PACKN 2820         // packed array with sentinel pad (reads up to index 2819)

#define BYTEJ(j) ((int)((bw[(j) >> 2] >> (((j) & 3) * 8)) & 0xFF))

__device__ __forceinline__ unsigned compose4(unsigned e0, unsigned e1, unsigned e2,
                                             unsigned e3, unsigned p) {
    // apply p (earlier map) first, then own map {e0..e3}; value = (count<<2)|exit_off
    unsigned r1 = p & 3u;
    unsigned a   = (r1 & 1u) ? e1 : e0;
    unsigned bb_ = (r1 & 1u) ? e3 : e2;
    unsigned own = (r1 & 2u) ? bb_ : a;
    return own + (p & ~3u);
}

__global__ __launch_bounds__(256)
void patcher_kernel(const int* __restrict__ x,
                    const float* __restrict__ w1,
                    const float* __restrict__ b1,
                    const float* __restrict__ w2,
                    const float* __restrict__ b2,
                    float* __restrict__ out_feat,   // [B,E]
                    float* __restrict__ out_ent)    // [B,L]
{
    __shared__ int      packed_s[PACKN];     // (cs3<<1)|bit, sentinels 0 beyond M3
    __shared__ int      hist_s[8 * 64];      // per-warp histograms over q in [0,48]
    __shared__ int      hist_tot_s[52];
    __shared__ unsigned wm_s[32];            // 8 warp maps x 4 entries
    __shared__ unsigned wb0_s[12];           // exclusive warp-base maps at entry 0
    __shared__ unsigned g0_s[256];           // inclusive composite evaluated at 0
    __shared__ int      warp_sums_s[8];
    __shared__ int      wbase8_s[8];
    __shared__ int      total_sm;
    __shared__ float    clip_mean_s;
    __shared__ int      clip_flag_s;
    __shared__ float    hpart_s[4 * EE];
    __shared__ float    havg_s[EE];

    const int b = blockIdx.x;
    const int t = threadIdx.x;
    const int lane = t & 31;
    const int wid  = t >> 5;
    const unsigned FULL = 0xffffffffu;
    const int* __restrict__ xrow = x + (long)b * LL;

    // ---- register tables broadcast via shfl (lane c holds entry c) ----
    float fl    = (float)lane;
    float clogv = (lane >= 2) ? fl * log2f(fl) : 0.0f;   // c*log2(c)
    float fl1   = fl + 1.0f;
    float dtabv = fl1 * log2f(fl1) - clogv;              // dlog(c) = (c+1)lg(c+1)-c*lg(c)

    // ---- init smem ----
    hist_s[t] = 0;
    hist_s[t + 256] = 0;
    if (t < PACKN - M3) packed_s[M3 + t] = 0;
    if (t == 0) { clip_flag_s = 0; clip_mean_s = 0.0f; }

    // ================= phase 0: window load + entropy + emit =================
    // tokens [32t-8, 32t+36) as 11 packed-byte u32 (clamped int4 loads; clamped
    // bytes are never consumed thanks to the boundary gating below)
    unsigned bw[11];
    {
        const int4* xv4 = (const int4*)xrow;
        #pragma unroll
        for (int q = 0; q < 11; q++) {
            int gi = 8 * t - 2 + q;
            gi = gi < 0 ? 0 : (gi > 2047 ? 2047 : gi);
            int4 v = xv4[gi];
            bw[q] = (unsigned)v.x | ((unsigned)v.y << 8) |
                    ((unsigned)v.z << 16) | ((unsigned)v.w << 24);
        }
    }

    // initial histogram for i0 = 32t: window tokens [i0-4, i0+4] = bytes 4..12
    int hp = 0;
    {
        const int jj0 = (t == 0) ? 8 : 4;   // thread 0: window [0,4] = bytes 8..12
        #pragma unroll
        for (int jj = 4; jj <= 12; jj++) {
            if (jj >= jj0) hp += 1 << (BYTEJ(jj) * 6);
        }
    }
    float S = 0.0f;
    #pragma unroll
    for (int q = 0; q < 5; q++) {
        int c = (hp >> (6 * q)) & 63;
        S += __shfl_sync(FULL, clogv, c);
    }

    int rr   = (2 * t) % 3;              // i % 3 for i = 32t
    int mreg = (32 * t + 2) / 3;         // first m with 3m >= 32t
    const int mlo = mreg;
    int run = 0;                         // sum of tokens [32t, i)
    float* erow = out_ent + (long)b * LL + 32 * t;
    float4 ebuf;

    #pragma unroll
    for (int k = 0; k < 32; k++) {
        // entropy at i = 32t + k (window histogram is in hp/S)
        float ent = 3.16992500144f - S * (1.0f / 9.0f);    // interior: tot=9
        if (t == 0) {
            if (k == 0)      ent = 2.32192809489f - S * 0.2f;          // tot=5
            else if (k == 1) ent = 2.58496250072f - S * (1.0f/6.0f);   // tot=6
            else if (k == 2) ent = 2.80735492206f - S * (1.0f/7.0f);   // tot=7
            else if (k == 3) ent = 3.0f           - S * 0.125f;        // tot=8
        }
        if (t == 255) {
            if (k == 28)      ent = 3.0f           - S * 0.125f;
            else if (k == 29) ent = 2.80735492206f - S * (1.0f/7.0f);
            else if (k == 30) ent = 2.58496250072f - S * (1.0f/6.0f);
            else if (k == 31) ent = 2.32192809489f - S * 0.2f;
        }
        if      ((k & 3) == 0) ebuf.x = ent;
        else if ((k & 3) == 1) ebuf.y = ent;
        else if ((k & 3) == 2) ebuf.z = ent;
        else {
            ebuf.w = ent;
            *reinterpret_cast<float4*>(erow + (k - 3)) = ebuf;
        }

        // emit (pre-cs3, bit) at patch-grid positions i % 3 == 0
        if (rr == 0) {
            packed_s[mreg] = (run << 1) | (ent > 1.5f ? 1 : 0);
            mreg++;
        }
        rr = (rr == 2) ? 0 : rr + 1;
        run += BYTEJ(k + 8);             // token i

        // slide i -> i+1: drop token i-4 (byte k+4), add token i+5 (byte k+13)
        if (k < 31) {
            int sh1 = BYTEJ(k + 4) * 6;
            int c_out = (hp >> sh1) & 63;
            int ci = c_out - 1; if (ci < 0) ci = 0;
            float dl_out = __shfl_sync(FULL, dtabv, ci);
            if (k >= 4 || t != 0) { hp -= 1 << sh1; S -= dl_out; }
            int sh2 = BYTEJ(k + 13) * 6;
            int c_in = (hp >> sh2) & 63;
            float dl_in = __shfl_sync(FULL, dtabv, c_in);
            if (k < 27 || t != 255) { hp += 1 << sh2; S += dl_in; }
        }
    }
    const int mhi = mreg;   // one past last emitted m for this thread

    // ---- block exclusive scan of per-thread 32-token sums ----
    int v = run;
    #pragma unroll
    for (int d = 1; d < 32; d <<= 1) {
        int n = __shfl_up_sync(FULL, v, d);
        if (lane >= d) v += n;
    }
    if (lane == 31) warp_sums_s[wid] = v;
    int excl = v - run;
    __syncthreads();

    if (wid == 0) {
        int ws = (lane < 8) ? warp_sums_s[lane] : 0;
        int vv = ws;
        #pragma unroll
        for (int d = 1; d < 8; d <<= 1) {
            int n = __shfl_up_sync(FULL, vv, d);
            if (lane >= d) vv += n;
        }
        if (lane < 8) wbase8_s[lane] = vv - ws;  // exclusive
        if (lane == 7) total_sm = vv;
    }
    __syncthreads();

    // ================= cs3 base fixup + phase A (4 chains/chunk) =============
    {
        int base2 = (wbase8_s[wid] + excl) << 1;
        for (int m2 = mlo; m2 < mhi; m2++) packed_s[m2] += base2;
        // NOTE: phase A below reads only the LSB (unchanged by the word-atomic
        // += above); full words are consumed only after later __syncthreads.
    }

    unsigned e0, e1, e2, e3;
    {
        const int mend = CH * (t + 1);
        int mm0 = CH * t + 0, mm1 = CH * t + 1, mm2 = CH * t + 2, mm3 = CH * t + 3;
        int cc0 = 0, cc1 = 0, cc2 = 0, cc3 = 0;
        #pragma unroll
        for (int it = 0; it < CH; it++) {
            int pk0 = packed_s[mm0], pk1 = packed_s[mm1];
            int pk2 = packed_s[mm2], pk3 = packed_s[mm3];
            bool a0 = mm0 < mend, a1 = mm1 < mend, a2 = mm2 < mend, a3 = mm3 < mend;
            cc0 += (a0 && mm0 < M3) ? 1 : 0;
            cc1 += (a1 && mm1 < M3) ? 1 : 0;
            cc2 += (a2 && mm2 < M3) ? 1 : 0;
            cc3 += (a3 && mm3 < M3) ? 1 : 0;
            mm0 += a0 ? ((pk0 & 1) ? 1 : 4) : 0;
            mm1 += a1 ? ((pk1 & 1) ? 1 : 4) : 0;
            mm2 += a2 ? ((pk2 & 1) ? 1 : 4) : 0;
            mm3 += a3 ? ((pk3 & 1) ? 1 : 4) : 0;
        }
        e0 = ((unsigned)cc0 << 2) | (unsigned)(mm0 - mend);
        e1 = ((unsigned)cc1 << 2) | (unsigned)(mm1 - mend);
        e2 = ((unsigned)cc2 << 2) | (unsigned)(mm2 - mend);
        e3 = ((unsigned)cc3 << 2) | (unsigned)(mm3 - mend);
    }

    // ---- intra-warp inclusive composition scan ----
    #pragma unroll
    for (int d = 1; d < 32; d <<= 1) {
        unsigned p0 = __shfl_up_sync(FULL, e0, d);
        unsigned p1 = __shfl_up_sync(FULL, e1, d);
        unsigned p2 = __shfl_up_sync(FULL, e2, d);
        unsigned p3 = __shfl_up_sync(FULL, e3, d);
        if (lane >= d) {
            unsigned n0 = compose4(e0, e1, e2, e3, p0);
            unsigned n1 = compose4(e0, e1, e2, e3, p1);
            unsigned n2 = compose4(e0, e1, e2, e3, p2);
            unsigned n3 = compose4(e0, e1, e2, e3, p3);
            e0 = n0; e1 = n1; e2 = n2; e3 = n3;
        }
    }
    if (lane == 31) {
        wm_s[wid * 4 + 0] = e0; wm_s[wid * 4 + 1] = e1;
        wm_s[wid * 4 + 2] = e2; wm_s[wid * 4 + 3] = e3;
    }
    __syncthreads();

    // ---- inter-warp composition scan of the 8 warp maps (warp 0) ----
    if (wid == 0) {
        unsigned f0 = (lane < 8) ? wm_s[lane * 4 + 0] : 0u;
        unsigned f1 = (lane < 8) ? wm_s[lane * 4 + 1] : 1u;
        unsigned f2 = (lane < 8) ? wm_s[lane * 4 + 2] : 2u;
        unsigned f3 = (lane < 8) ? wm_s[lane * 4 + 3] : 3u;
        #pragma unroll
        for (int d = 1; d < 8; d <<= 1) {
            unsigned p0 = __shfl_up_sync(FULL, f0, d);
            unsigned p1 = __shfl_up_sync(FULL, f1, d);
            unsigned p2 = __shfl_up_sync(FULL, f2, d);
            unsigned p3 = __shfl_up_sync(FULL, f3, d);
            if (lane >= d && lane < 8) {
                unsigned n0 = compose4(f0, f1, f2, f3, p0);
                unsigned n1 = compose4(f0, f1, f2, f3, p1);
                unsigned n2 = compose4(f0, f1, f2, f3, p2);
                unsigned n3 = compose4(f0, f1, f2, f3, p3);
                f0 = n0; f1 = n1; f2 = n2; f3 = n3;
            }
        }
        if (lane < 8)   wb0_s[lane + 1] = f0;   // exclusive base for warp lane+1
        if (lane == 31) wb0_s[0] = 0u;          // identity (chain starts m=0, off 0)
    }
    __syncthreads();

    // ---- inclusive composite for every chunk, evaluated at entry 0 ----
    g0_s[t] = compose4(e0, e1, e2, e3, wb0_s[wid]);
    __syncthreads();

    // ================= phase B: walk real path, histogram patch sums =========
    {
        unsigned ge = (t == 0) ? 0u : g0_s[t - 1];
        int m = CH * t + (int)(ge & 3u);
        const int mend = CH * (t + 1);
        const int totalv = total_sm;
        int* hw = &hist_s[wid * 64];
        while (m < mend) {
            int pk  = packed_s[m];
            int bit = pk & 1;
            int s   = bit ? 1 : 4;
            if (m < M3) {
                if (m + s <= M3 - 1) {
                    int sum = (packed_s[m + s] >> 1) - (pk >> 1);
                    int q = bit ? (sum << 2) : sum;    // mean = q/12
                    atomicAdd(&hw[q], 1);
                } else {
                    // clipped final patch: j = L (exactly one per row)
                    clip_mean_s = (float)(totalv - (pk >> 1)) / (float)(LL - 3 * m);
                    clip_flag_s = 1;
                }
            }
            m += s;
        }
    }
    __syncthreads();

    // ---- reduce per-warp histograms ----
    if (t < 49) {
        int s = 0;
        #pragma unroll
        for (int w = 0; w < 8; w++) s += hist_s[w * 64 + t];
        hist_tot_s[t] = s;
    }
    __syncthreads();

    // ================= MLP: hist-weighted relu accumulate ====================
    {
        int e = t & 63;
        int g = t >> 6;
        float w1e = w1[e];
        float b1e = b1[e];
        float acc = 0.0f;
        int q0 = g * 13;
        int q1 = q0 + 13; if (q1 > 49) q1 = 49;
        for (int q = q0; q < q1; q++) {
            int c = hist_tot_s[q];
            if (c) acc += (float)c * fmaxf(fmaf((float)q * (1.0f / 12.0f), w1e, b1e), 0.0f);
        }
        if (g == 0 && clip_flag_s)
            acc += fmaxf(fmaf(clip_mean_s, w1e, b1e), 0.0f);
        hpart_s[g * EE + e] = acc;
    }
    __syncthreads();

    if (t < EE) {
        float npf = (float)(g0_s[255] >> 2);   // total valid patch count
        havg_s[t] = (hpart_s[t] + hpart_s[EE + t] +
                     hpart_s[2 * EE + t] + hpart_s[3 * EE + t]) / npf;
    }
    __syncthreads();

    // ---- final 64x64 GEMV ----
    if (t < EE) {
        const float4* w2r = reinterpret_cast<const float4*>(w2 + t * EE);
        float f = b2[t];
        #pragma unroll
        for (int kk = 0; kk < 16; kk++) {
            float4 wv = w2r[kk];
            f = fmaf(havg_s[4 * kk + 0], wv.x, f);
            f = fmaf(havg_s[4 * kk + 1], wv.y, f);
            f = fmaf(havg_s[4 * kk + 2], wv.z, f);
            f = fmaf(havg_s[4 * kk + 3], wv.w, f);
        }
        out_feat[(long)b * EE + t] = f;
    }
}

extern "C" void kernel_launch(void* const* d_in, const int* in_sizes, int n_in,
                              void* d_out, int out_size) {
    const int*   x  = (const int*)d_in[0];
    const float* w1 = (const float*)d_in[1];
    const float* b1 = (const float*)d_in[2];
    const float* w2 = (const float*)d_in[3];
    const float* b2 = (const float*)d_in[4];
    float* out = (float*)d_out;
    patcher_kernel<<<BB, 256>>>(x, w1, b1, w2, b2, out, out + BB * EE);
}

// round 4
// speedup vs baseline: 2.0173x; 1.1330x over previous
#include <cuda_runtime.h>
#include <stdint.h>

#define BB 256
#define LL 8192
#define EE 64
#define M3 2731            // ceil(L/3) chain nodes (patch starts are multiples of 3)
#define CH 11              // m-nodes per chunk, 256 chunks: 256*11 = 2816 >= 2731
#define PACKN 2820         // packed array with sentinel pad (reads up to index 2819)

// dynamic smem layout
#define STAGE_WORDS 2304         // 2048 + 2048/8 padding
#define OFF_STAGE  0
#define OFF_EBUF   9216          // 8 warps * 1056 floats = 33792 B
#define OFF_PACKED (9216 + 33792)            // 2820 ints = 11280 B
#define OFF_HIST   (9216 + 33792 + 11280)    // 512 ints  = 2048 B
#define SMEM_DYN   (9216 + 33792 + 11280 + 2048)

#define BYTEJ(j) ((int)((bw[(j) >> 2] >> (((j) & 3) * 8)) & 0xFF))

__device__ __forceinline__ unsigned compose4(unsigned e0, unsigned e1, unsigned e2,
                                             unsigned e3, unsigned p) {
    // apply p (earlier map) first, then own map {e0..e3}; value = (count<<2)|exit_off
    unsigned r1 = p & 3u;
    unsigned a   = (r1 & 1u) ? e1 : e0;
    unsigned bb_ = (r1 & 1u) ? e3 : e2;
    unsigned own = (r1 & 2u) ? bb_ : a;
    return own + (p & ~3u);
}

__global__ __launch_bounds__(256)
void patcher_kernel(const int* __restrict__ x,
                    const float* __restrict__ w1,
                    const float* __restrict__ b1,
                    const float* __restrict__ w2,
                    const float* __restrict__ b2,
                    float* __restrict__ out_feat,   // [B,E]
                    float* __restrict__ out_ent)    // [B,L]
{
    extern __shared__ char dynsmem[];
    uint32_t* stage_s  = (uint32_t*)(dynsmem + OFF_STAGE);   // padded packed bytes
    float*    ebuf_all = (float*)  (dynsmem + OFF_EBUF);     // 8 x 1056 (stride 33)
    int*      packed_s = (int*)    (dynsmem + OFF_PACKED);   // (cs3<<1)|bit
    int*      hist_s   = (int*)    (dynsmem + OFF_HIST);     // 8 warps x 64 bins

    __shared__ int      hist_tot_s[52];
    __shared__ unsigned wm_s[32];
    __shared__ unsigned wb0_s[12];
    __shared__ unsigned g0_s[256];
    __shared__ int      warp_sums_s[8];
    __shared__ int      wbase8_s[8];
    __shared__ int      total_sm;
    __shared__ float    clip_mean_s;
    __shared__ int      clip_flag_s;
    __shared__ float    hpart_s[4 * EE];
    __shared__ float    havg_s[EE];

    const int b = blockIdx.x;
    const int t = threadIdx.x;
    const int lane = t & 31;
    const int wid  = t >> 5;
    const unsigned FULL = 0xffffffffu;
    const int* __restrict__ xrow = x + (long)b * LL;

    // ---- register tables broadcast via shfl (lane c holds entry c) ----
    float fl    = (float)lane;
    float clogv = (lane >= 2) ? fl * log2f(fl) : 0.0f;   // c*log2(c)
    float fl1   = fl + 1.0f;
    float dtabv = fl1 * log2f(fl1) - clogv;              // dlog(c)

    // ---- init smem ----
    hist_s[t] = 0;
    hist_s[t + 256] = 0;
    if (t < PACKN - M3) packed_s[M3 + t] = 0;
    if (t == 0) { clip_flag_s = 0; clip_mean_s = 0.0f; }

    // ---- coalesced gmem load -> bank-padded byte staging ----
    // word w holds tokens [4w, 4w+4) packed as bytes; stored at w + (w>>3)
    {
        const int4* xv4 = (const int4*)xrow;
        #pragma unroll
        for (int j = 0; j < 8; j++) {
            int w = t + 256 * j;
            int4 v = xv4[w];
            uint32_t pk = (unsigned)v.x | ((unsigned)v.y << 8) |
                          ((unsigned)v.z << 16) | ((unsigned)v.w << 24);
            stage_s[w + (w >> 3)] = pk;
        }
    }
    __syncthreads();

    // ---- window words for this thread: bw[q] = word 8t-2+q, q=1..10 ----
    // (bytes 0..3 of bw[0] are never consumed; clamped edge words are gated)
    unsigned bw[11];
    bw[0] = 0u;
    #pragma unroll
    for (int q = 1; q < 11; q++) {
        int w = 8 * t - 2 + q;
        w = w < 0 ? 0 : (w > 2047 ? 2047 : w);
        bw[q] = stage_s[w + (w >> 3)];
    }

    // initial histogram for i0 = 32t: window tokens [i0-4, i0+4] = bytes 4..12
    int hp = 0;
    {
        const int jj0 = (t == 0) ? 8 : 4;
        #pragma unroll
        for (int jj = 4; jj <= 12; jj++) {
            if (jj >= jj0) hp += 1 << (BYTEJ(jj) * 6);
        }
    }
    float S = 0.0f;
    #pragma unroll
    for (int q = 0; q < 5; q++) {
        int c = (hp >> (6 * q)) & 63;
        S += __shfl_sync(FULL, clogv, c);
    }

    int rr   = (2 * t) % 3;              // i % 3 for i = 32t
    int mreg = (32 * t + 2) / 3;         // first m with 3m >= 32t
    const int mlo = mreg;
    int run = 0;                         // sum of tokens [32t, i)
    float* ebuf = ebuf_all + wid * 1056 + lane * 33;

    #pragma unroll
    for (int k = 0; k < 32; k++) {
        float ent = 3.16992500144f - S * (1.0f / 9.0f);    // interior: tot=9
        if (t == 0) {
            if (k == 0)      ent = 2.32192809489f - S * 0.2f;
            else if (k == 1) ent = 2.58496250072f - S * (1.0f/6.0f);
            else if (k == 2) ent = 2.80735492206f - S * (1.0f/7.0f);
            else if (k == 3) ent = 3.0f           - S * 0.125f;
        }
        if (t == 255) {
            if (k == 28)      ent = 3.0f           - S * 0.125f;
            else if (k == 29) ent = 2.80735492206f - S * (1.0f/7.0f);
            else if (k == 30) ent = 2.58496250072f - S * (1.0f/6.0f);
            else if (k == 31) ent = 2.32192809489f - S * 0.2f;
        }
        ebuf[k] = ent;                    // conflict-free (stride 33)

        if (rr == 0) {
            packed_s[mreg] = (run << 1) | (ent > 1.5f ? 1 : 0);
            mreg++;
        }
        rr = (rr == 2) ? 0 : rr + 1;
        run += BYTEJ(k + 8);             // token i

        // slide i -> i+1: drop token i-4 (byte k+4), add token i+5 (byte k+13)
        if (k < 31) {
            int sh1 = BYTEJ(k + 4) * 6;
            int c_out = (hp >> sh1) & 63;
            int ci = c_out - 1; if (ci < 0) ci = 0;
            float dl_out = __shfl_sync(FULL, dtabv, ci);
            if (k >= 4 || t != 0) { hp -= 1 << sh1; S -= dl_out; }
            int sh2 = BYTEJ(k + 13) * 6;
            int c_in = (hp >> sh2) & 63;
            float dl_in = __shfl_sync(FULL, dtabv, c_in);
            if (k < 27 || t != 255) { hp += 1 << sh2; S += dl_in; }
        }
    }
    const int mhi = mreg;

    // ---- coalesced entropy flush (per-warp tile of 1024 floats) ----
    __syncwarp();
    {
        const float* eb = ebuf_all + wid * 1056;
        float* erow_w = out_ent + (long)b * LL + 1024 * wid;
        #pragma unroll
        for (int j = 0; j < 8; j++) {
            int m  = 4 * j + (lane >> 3);
            int k0 = 4 * (lane & 7);
            const float* src = eb + m * 33 + k0;
            float4 v;
            v.x = src[0]; v.y = src[1]; v.z = src[2]; v.w = src[3];
            *reinterpret_cast<float4*>(erow_w + 32 * m + k0) = v;
        }
    }

    // ---- block exclusive scan of per-thread 32-token sums ----
    int v = run;
    #pragma unroll
    for (int d = 1; d < 32; d <<= 1) {
        int n = __shfl_up_sync(FULL, v, d);
        if (lane >= d) v += n;
    }
    if (lane == 31) warp_sums_s[wid] = v;
    int excl = v - run;
    __syncthreads();

    if (wid == 0) {
        int ws = (lane < 8) ? warp_sums_s[lane] : 0;
        int vv = ws;
        #pragma unroll
        for (int d = 1; d < 8; d <<= 1) {
            int n = __shfl_up_sync(FULL, vv, d);
            if (lane >= d) vv += n;
        }
        if (lane < 8) wbase8_s[lane] = vv - ws;  // exclusive
        if (lane == 7) total_sm = vv;
    }
    __syncthreads();

    // ================= cs3 base fixup + phase A (4 chains/chunk) =============
    {
        int base2 = (wbase8_s[wid] + excl) << 1;
        for (int m2 = mlo; m2 < mhi; m2++) packed_s[m2] += base2;
        // phase A reads only the LSB (unchanged by the += above); full words
        // are consumed only after the next __syncthreads.
    }

    unsigned e0, e1, e2, e3;
    {
        const int mend = CH * (t + 1);
        int mm0 = CH * t + 0, mm1 = CH * t + 1, mm2 = CH * t + 2, mm3 = CH * t + 3;
        int cc0 = 0, cc1 = 0, cc2 = 0, cc3 = 0;
        #pragma unroll
        for (int it = 0; it < CH; it++) {
            int pk0 = packed_s[mm0], pk1 = packed_s[mm1];
            int pk2 = packed_s[mm2], pk3 = packed_s[mm3];
            bool a0 = mm0 < mend, a1 = mm1 < mend, a2 = mm2 < mend, a3 = mm3 < mend;
            cc0 += (a0 && mm0 < M3) ? 1 : 0;
            cc1 += (a1 && mm1 < M3) ? 1 : 0;
            cc2 += (a2 && mm2 < M3) ? 1 : 0;
            cc3 += (a3 && mm3 < M3) ? 1 : 0;
            mm0 += a0 ? ((pk0 & 1) ? 1 : 4) : 0;
            mm1 += a1 ? ((pk1 & 1) ? 1 : 4) : 0;
            mm2 += a2 ? ((pk2 & 1) ? 1 : 4) : 0;
            mm3 += a3 ? ((pk3 & 1) ? 1 : 4) : 0;
        }
        e0 = ((unsigned)cc0 << 2) | (unsigned)(mm0 - mend);
        e1 = ((unsigned)cc1 << 2) | (unsigned)(mm1 - mend);
        e2 = ((unsigned)cc2 << 2) | (unsigned)(mm2 - mend);
        e3 = ((unsigned)cc3 << 2) | (unsigned)(mm3 - mend);
    }

    // ---- intra-warp inclusive composition scan ----
    #pragma unroll
    for (int d = 1; d < 32; d <<= 1) {
        unsigned p0 = __shfl_up_sync(FULL, e0, d);
        unsigned p1 = __shfl_up_sync(FULL, e1, d);
        unsigned p2 = __shfl_up_sync(FULL, e2, d);
        unsigned p3 = __shfl_up_sync(FULL, e3, d);
        if (lane >= d) {
            unsigned n0 = compose4(e0, e1, e2, e3, p0);
            unsigned n1 = compose4(e0, e1, e2, e3, p1);
            unsigned n2 = compose4(e0, e1, e2, e3, p2);
            unsigned n3 = compose4(e0, e1, e2, e3, p3);
            e0 = n0; e1 = n1; e2 = n2; e3 = n3;
        }
    }
    if (lane == 31) {
        wm_s[wid * 4 + 0] = e0; wm_s[wid * 4 + 1] = e1;
        wm_s[wid * 4 + 2] = e2; wm_s[wid * 4 + 3] = e3;
    }
    __syncthreads();

    // ---- inter-warp composition scan of the 8 warp maps (warp 0) ----
    if (wid == 0) {
        unsigned f0 = (lane < 8) ? wm_s[lane * 4 + 0] : 0u;
        unsigned f1 = (lane < 8) ? wm_s[lane * 4 + 1] : 1u;
        unsigned f2 = (lane < 8) ? wm_s[lane * 4 + 2] : 2u;
        unsigned f3 = (lane < 8) ? wm_s[lane * 4 + 3] : 3u;
        #pragma unroll
        for (int d = 1; d < 8; d <<= 1) {
            unsigned p0 = __shfl_up_sync(FULL, f0, d);
            unsigned p1 = __shfl_up_sync(FULL, f1, d);
            unsigned p2 = __shfl_up_sync(FULL, f2, d);
            unsigned p3 = __shfl_up_sync(FULL, f3, d);
            if (lane >= d && lane < 8) {
                unsigned n0 = compose4(f0, f1, f2, f3, p0);
                unsigned n1 = compose4(f0, f1, f2, f3, p1);
                unsigned n2 = compose4(f0, f1, f2, f3, p2);
                unsigned n3 = compose4(f0, f1, f2, f3, p3);
                f0 = n0; f1 = n1; f2 = n2; f3 = n3;
            }
        }
        if (lane < 8)   wb0_s[lane + 1] = f0;
        if (lane == 31) wb0_s[0] = 0u;
    }
    __syncthreads();

    // ---- inclusive composite for every chunk, evaluated at entry 0 ----
    g0_s[t] = compose4(e0, e1, e2, e3, wb0_s[wid]);
    __syncthreads();

    // ================= phase B: walk real path, histogram patch sums =========
    {
        unsigned ge = (t == 0) ? 0u : g0_s[t - 1];
        int m = CH * t + (int)(ge & 3u);
        const int mend = CH * (t + 1);
        const int totalv = total_sm;
        int* hw = &hist_s[wid * 64];
        while (m < mend) {
            int pk  = packed_s[m];
            int bit = pk & 1;
            int s   = bit ? 1 : 4;
            if (m < M3) {
                if (m + s <= M3 - 1) {
                    int sum = (packed_s[m + s] >> 1) - (pk >> 1);
                    int q = bit ? (sum << 2) : sum;    // mean = q/12
                    atomicAdd(&hw[q], 1);
                } else {
                    clip_mean_s = (float)(totalv - (pk >> 1)) / (float)(LL - 3 * m);
                    clip_flag_s = 1;
                }
            }
            m += s;
        }
    }
    __syncthreads();

    // ---- reduce per-warp histograms ----
    if (t < 49) {
        int s = 0;
        #pragma unroll
        for (int w = 0; w < 8; w++) s += hist_s[w * 64 + t];
        hist_tot_s[t] = s;
    }
    __syncthreads();

    // ================= MLP: hist-weighted relu accumulate ====================
    {
        int e = t & 63;
        int g = t >> 6;
        float w1e = w1[e];
        float b1e = b1[e];
        float acc = 0.0f;
        int q0 = g * 13;
        int q1 = q0 + 13; if (q1 > 49) q1 = 49;
        for (int q = q0; q < q1; q++) {
            int c = hist_tot_s[q];
            if (c) acc += (float)c * fmaxf(fmaf((float)q * (1.0f / 12.0f), w1e, b1e), 0.0f);
        }
        if (g == 0 && clip_flag_s)
            acc += fmaxf(fmaf(clip_mean_s, w1e, b1e), 0.0f);
        hpart_s[g * EE + e] = acc;
    }
    __syncthreads();

    if (t < EE) {
        float npf = (float)(g0_s[255] >> 2);
        havg_s[t] = (hpart_s[t] + hpart_s[EE + t] +
                     hpart_s[2 * EE + t] + hpart_s[3 * EE + t]) / npf;
    }
    __syncthreads();

    // ---- final 64x64 GEMV ----
    if (t < EE) {
        const float4* w2r = reinterpret_cast<const float4*>(w2 + t * EE);
        float f = b2[t];
        #pragma unroll
        for (int kk = 0; kk < 16; kk++) {
            float4 wv = w2r[kk];
            f = fmaf(havg_s[4 * kk + 0], wv.x, f);
            f = fmaf(havg_s[4 * kk + 1], wv.y, f);
            f = fmaf(havg_s[4 * kk + 2], wv.z, f);
            f = fmaf(havg_s[4 * kk + 3], wv.w, f);
        }
        out_feat[(long)b * EE + t] = f;
    }
}

extern "C" void kernel_launch(void* const* d_in, const int* in_sizes, int n_in,
                              void* d_out, int out_size) {
    const int*   x  = (const int*)d_in[0];
    const float* w1 = (const float*)d_in[1];
    const float* b1 = (const float*)d_in[2];
    const float* w2 = (const float*)d_in[3];
    const float* b2 = (const float*)d_in[4];
    float* out = (float*)d_out;
    cudaFuncSetAttribute(patcher_kernel,
                         cudaFuncAttributeMaxDynamicSharedMemorySize, SMEM_DYN);
    patcher_kernel<<<BB, 256, SMEM_DYN>>>(x, w1, b1, w2, b2, out, out + BB * EE);
}

// round 5
// speedup vs baseline: 2.1832x; 1.0822x over previous
#include <cuda_runtime.h>
#include <stdint.h>

#define BB 256
#define LL 8192
#define EE 64
#define M3 2731            // ceil(L/3) chain nodes (patch starts are multiples of 3)
#define NT 512             // threads per block (one row per block)
#define CH 6               // m-nodes per chunk, 512 chunks: 512*6 = 3072 >= 2731
#define PACKN 3080         // padded packed array (reads up to index 3075)

#define BYTEJ(j) ((int)((bw[(j) >> 2] >> (((j) & 3) * 8)) & 0xFF))

__device__ __forceinline__ unsigned compose4(unsigned e0, unsigned e1, unsigned e2,
                                             unsigned e3, unsigned p) {
    // apply p (earlier map) first, then own map {e0..e3}; value = (count<<2)|exit_off
    unsigned r1 = p & 3u;
    unsigned a   = (r1 & 1u) ? e1 : e0;
    unsigned bb_ = (r1 & 1u) ? e3 : e2;
    unsigned own = (r1 & 2u) ? bb_ : a;
    return own + (p & ~3u);
}

__global__ __launch_bounds__(NT, 2)
void patcher_kernel(const int* __restrict__ x,
                    const float* __restrict__ w1,
                    const float* __restrict__ b1,
                    const float* __restrict__ w2,
                    const float* __restrict__ b2,
                    float* __restrict__ out_feat,   // [B,E]
                    float* __restrict__ out_ent)    // [B,L]
{
    __shared__ uint32_t stage_s[2304];       // 2048 words + bank padding (w + w>>3)
    __shared__ int      packed_s[PACKN];     // (cs3<<1)|bit, sentinels 0 beyond M3
    __shared__ int      hist_s[16 * 64];     // per-warp histograms over q in [0,48]
    __shared__ int      hist_tot_s[52];
    __shared__ unsigned wm_s[64];            // 16 warp maps x 4 entries
    __shared__ unsigned wb0_s[17];           // exclusive warp-base maps at entry 0
    __shared__ unsigned g0_s[NT];            // inclusive composite evaluated at 0
    __shared__ int      warp_sums_s[16];
    __shared__ int      wbase16_s[16];
    __shared__ int      total_sm;
    __shared__ float    clip_mean_s;
    __shared__ int      clip_flag_s;
    __shared__ float    hpart_s[8 * EE];
    __shared__ float    havg_s[EE];

    const int b = blockIdx.x;
    const int t = threadIdx.x;
    const int lane = t & 31;
    const int wid  = t >> 5;                 // 0..15
    const unsigned FULL = 0xffffffffu;
    const int* __restrict__ xrow = x + (long)b * LL;

    // ---- register tables broadcast via shfl (lane c holds entry c) ----
    float fl    = (float)lane;
    float clogv = (lane >= 2) ? fl * log2f(fl) : 0.0f;   // c*log2(c)
    float fl1   = fl + 1.0f;
    float dtabv = fl1 * log2f(fl1) - clogv;              // dlog(c)

    // ---- init smem ----
    hist_s[t] = 0;
    hist_s[t + NT] = 0;
    if (t < PACKN - M3) packed_s[M3 + t] = 0;
    if (t == 0) { clip_flag_s = 0; clip_mean_s = 0.0f; }

    // ---- coalesced gmem load -> bank-padded byte staging ----
    // word w holds tokens [4w, 4w+4) packed as bytes; stored at w + (w>>3)
    {
        const int4* xv4 = (const int4*)xrow;
        #pragma unroll
        for (int j = 0; j < 4; j++) {
            int w = t + NT * j;
            int4 v = xv4[w];
            uint32_t pk = (unsigned)v.x | ((unsigned)v.y << 8) |
                          ((unsigned)v.z << 16) | ((unsigned)v.w << 24);
            stage_s[w + (w >> 3)] = pk;
        }
    }
    __syncthreads();

    // ---- window words: bw[q] = word 4t-1+q, covering tokens [16t-4, 16t+20) ----
    unsigned bw[6];
    #pragma unroll
    for (int q = 0; q < 6; q++) {
        int w = 4 * t - 1 + q;
        w = w < 0 ? 0 : (w > 2047 ? 2047 : w);
        bw[q] = stage_s[w + (w >> 3)];
    }

    // initial histogram for i0 = 16t: window tokens [i0-4, i0+4] = bytes 0..8
    int hp = 0;
    {
        const int jj0 = (t == 0) ? 4 : 0;    // thread 0: window [0,4] = bytes 4..8
        #pragma unroll
        for (int jj = 0; jj <= 8; jj++) {
            if (jj >= jj0) hp += 1 << (BYTEJ(jj) * 6);
        }
    }
    float S = 0.0f;
    #pragma unroll
    for (int q = 0; q < 5; q++) {
        int c = (hp >> (6 * q)) & 63;
        S += __shfl_sync(FULL, clogv, c);
    }

    int rr   = t % 3;                    // i0 % 3 (16 = 1 mod 3)
    int mreg = (16 * t + 2) / 3;         // first m with 3m >= 16t
    const int mlo = mreg;
    int run = 0;                         // sum of tokens [16t, i)
    float* erow = out_ent + (long)b * LL + 16 * t;
    float4 ebuf;

    #pragma unroll
    for (int k = 0; k < 16; k++) {
        float ent = 3.16992500144f - S * (1.0f / 9.0f);    // interior: tot=9
        if (t == 0) {
            if (k == 0)      ent = 2.32192809489f - S * 0.2f;           // tot=5
            else if (k == 1) ent = 2.58496250072f - S * (1.0f/6.0f);    // tot=6
            else if (k == 2) ent = 2.80735492206f - S * (1.0f/7.0f);    // tot=7
            else if (k == 3) ent = 3.0f           - S * 0.125f;         // tot=8
        }
        if (t == NT - 1) {
            if (k == 12)      ent = 3.0f           - S * 0.125f;
            else if (k == 13) ent = 2.80735492206f - S * (1.0f/7.0f);
            else if (k == 14) ent = 2.58496250072f - S * (1.0f/6.0f);
            else if (k == 15) ent = 2.32192809489f - S * 0.2f;
        }
        if      ((k & 3) == 0) ebuf.x = ent;
        else if ((k & 3) == 1) ebuf.y = ent;
        else if ((k & 3) == 2) ebuf.z = ent;
        else {
            ebuf.w = ent;
            *reinterpret_cast<float4*>(erow + (k - 3)) = ebuf;
        }

        if (rr == 0) {
            packed_s[mreg] = (run << 1) | (ent > 1.5f ? 1 : 0);
            mreg++;
        }
        rr = (rr == 2) ? 0 : rr + 1;
        run += BYTEJ(k + 4);             // token i = 16t+k is byte k+4

        // slide i -> i+1: drop token i-4 (byte k), add token i+5 (byte k+9)
        if (k < 15) {
            int sh1 = BYTEJ(k) * 6;
            int c_out = (hp >> sh1) & 63;
            int ci = c_out - 1; if (ci < 0) ci = 0;
            float dl_out = __shfl_sync(FULL, dtabv, ci);
            if (k >= 4 || t != 0) { hp -= 1 << sh1; S -= dl_out; }
            int sh2 = BYTEJ(k + 9) * 6;
            int c_in = (hp >> sh2) & 63;
            float dl_in = __shfl_sync(FULL, dtabv, c_in);
            if (k <= 10 || t != NT - 1) { hp += 1 << sh2; S += dl_in; }
        }
    }
    const int mhi = mreg;

    // ---- block exclusive scan of per-thread 16-token sums ----
    int v = run;
    #pragma unroll
    for (int d = 1; d < 32; d <<= 1) {
        int n = __shfl_up_sync(FULL, v, d);
        if (lane >= d) v += n;
    }
    if (lane == 31) warp_sums_s[wid] = v;
    int excl = v - run;
    __syncthreads();

    if (wid == 0) {
        int ws = (lane < 16) ? warp_sums_s[lane] : 0;
        int vv = ws;
        #pragma unroll
        for (int d = 1; d < 16; d <<= 1) {
            int n = __shfl_up_sync(FULL, vv, d);
            if (lane >= d) vv += n;
        }
        if (lane < 16) wbase16_s[lane] = vv - ws;  // exclusive
        if (lane == 15) total_sm = vv;
    }
    __syncthreads();

    // ================= cs3 base fixup + phase A (4 chains/chunk) =============
    {
        int base2 = (wbase16_s[wid] + excl) << 1;
        for (int m2 = mlo; m2 < mhi; m2++) packed_s[m2] += base2;
        // phase A below reads only the LSB (unchanged by the even += above);
        // full words are consumed only after the next __syncthreads.
    }

    unsigned e0, e1, e2, e3;
    {
        const int mend = CH * (t + 1);
        int mm0 = CH * t + 0, mm1 = CH * t + 1, mm2 = CH * t + 2, mm3 = CH * t + 3;
        int cc0 = 0, cc1 = 0, cc2 = 0, cc3 = 0;
        #pragma unroll
        for (int it = 0; it < CH; it++) {
            int pk0 = packed_s[mm0], pk1 = packed_s[mm1];
            int pk2 = packed_s[mm2], pk3 = packed_s[mm3];
            bool a0 = mm0 < mend, a1 = mm1 < mend, a2 = mm2 < mend, a3 = mm3 < mend;
            cc0 += (a0 && mm0 < M3) ? 1 : 0;
            cc1 += (a1 && mm1 < M3) ? 1 : 0;
            cc2 += (a2 && mm2 < M3) ? 1 : 0;
            cc3 += (a3 && mm3 < M3) ? 1 : 0;
            mm0 += a0 ? ((pk0 & 1) ? 1 : 4) : 0;
            mm1 += a1 ? ((pk1 & 1) ? 1 : 4) : 0;
            mm2 += a2 ? ((pk2 & 1) ? 1 : 4) : 0;
            mm3 += a3 ? ((pk3 & 1) ? 1 : 4) : 0;
        }
        e0 = ((unsigned)cc0 << 2) | (unsigned)(mm0 - mend);
        e1 = ((unsigned)cc1 << 2) | (unsigned)(mm1 - mend);
        e2 = ((unsigned)cc2 << 2) | (unsigned)(mm2 - mend);
        e3 = ((unsigned)cc3 << 2) | (unsigned)(mm3 - mend);
    }

    // ---- intra-warp inclusive composition scan ----
    #pragma unroll
    for (int d = 1; d < 32; d <<= 1) {
        unsigned p0 = __shfl_up_sync(FULL, e0, d);
        unsigned p1 = __shfl_up_sync(FULL, e1, d);
        unsigned p2 = __shfl_up_sync(FULL, e2, d);
        unsigned p3 = __shfl_up_sync(FULL, e3, d);
        if (lane >= d) {
            unsigned n0 = compose4(e0, e1, e2, e3, p0);
            unsigned n1 = compose4(e0, e1, e2, e3, p1);
            unsigned n2 = compose4(e0, e1, e2, e3, p2);
            unsigned n3 = compose4(e0, e1, e2, e3, p3);
            e0 = n0; e1 = n1; e2 = n2; e3 = n3;
        }
    }
    if (lane == 31) {
        wm_s[wid * 4 + 0] = e0; wm_s[wid * 4 + 1] = e1;
        wm_s[wid * 4 + 2] = e2; wm_s[wid * 4 + 3] = e3;
    }
    __syncthreads();

    // ---- inter-warp composition scan of the 16 warp maps (warp 0) ----
    if (wid == 0) {
        unsigned f0 = (lane < 16) ? wm_s[lane * 4 + 0] : 0u;
        unsigned f1 = (lane < 16) ? wm_s[lane * 4 + 1] : 1u;
        unsigned f2 = (lane < 16) ? wm_s[lane * 4 + 2] : 2u;
        unsigned f3 = (lane < 16) ? wm_s[lane * 4 + 3] : 3u;
        #pragma unroll
        for (int d = 1; d < 16; d <<= 1) {
            unsigned p0 = __shfl_up_sync(FULL, f0, d);
            unsigned p1 = __shfl_up_sync(FULL, f1, d);
            unsigned p2 = __shfl_up_sync(FULL, f2, d);
            unsigned p3 = __shfl_up_sync(FULL, f3, d);
            if (lane >= d && lane < 16) {
                unsigned n0 = compose4(f0, f1, f2, f3, p0);
                unsigned n1 = compose4(f0, f1, f2, f3, p1);
                unsigned n2 = compose4(f0, f1, f2, f3, p2);
                unsigned n3 = compose4(f0, f1, f2, f3, p3);
                f0 = n0; f1 = n1; f2 = n2; f3 = n3;
            }
        }
        if (lane < 16)  wb0_s[lane + 1] = f0;
        if (lane == 31) wb0_s[0] = 0u;
    }
    __syncthreads();

    // ---- inclusive composite for every chunk, evaluated at entry 0 ----
    g0_s[t] = compose4(e0, e1, e2, e3, wb0_s[wid]);
    __syncthreads();

    // ================= phase B: walk real path, histogram patch sums =========
    {
        unsigned ge = (t == 0) ? 0u : g0_s[t - 1];
        int m = CH * t + (int)(ge & 3u);
        const int mend = CH * (t + 1);
        const int totalv = total_sm;
        int* hw = &hist_s[wid * 64];
        while (m < mend) {
            int pk  = packed_s[m];
            int bit = pk & 1;
            int s   = bit ? 1 : 4;
            if (m < M3) {
                if (m + s <= M3 - 1) {
                    int sum = (packed_s[m + s] >> 1) - (pk >> 1);
                    int q = bit ? (sum << 2) : sum;    // mean = q/12
                    atomicAdd(&hw[q], 1);
                } else {
                    clip_mean_s = (float)(totalv - (pk >> 1)) / (float)(LL - 3 * m);
                    clip_flag_s = 1;
                }
            }
            m += s;
        }
    }
    __syncthreads();

    // ---- reduce per-warp histograms ----
    if (t < 49) {
        int s = 0;
        #pragma unroll
        for (int w = 0; w < 16; w++) s += hist_s[w * 64 + t];
        hist_tot_s[t] = s;
    }
    __syncthreads();

    // ================= MLP: hist-weighted relu accumulate ====================
    {
        int e = t & 63;
        int g = t >> 6;                  // 0..7
        float w1e = w1[e];
        float b1e = b1[e];
        float acc = 0.0f;
        int q0 = g * 7;
        int q1 = q0 + 7; if (q1 > 49) q1 = 49;
        for (int q = q0; q < q1; q++) {
            int c = hist_tot_s[q];
            if (c) acc += (float)c * fmaxf(fmaf((float)q * (1.0f / 12.0f), w1e, b1e), 0.0f);
        }
        if (g == 0 && clip_flag_s)
            acc += fmaxf(fmaf(clip_mean_s, w1e, b1e), 0.0f);
        hpart_s[g * EE + e] = acc;
    }
    __syncthreads();

    if (t < EE) {
        float npf = (float)(g0_s[NT - 1] >> 2);
        float s = 0.0f;
        #pragma unroll
        for (int g = 0; g < 8; g++) s += hpart_s[g * EE + t];
        havg_s[t] = s / npf;
    }
    __syncthreads();

    // ---- final 64x64 GEMV ----
    if (t < EE) {
        const float4* w2r = reinterpret_cast<const float4*>(w2 + t * EE);
        float f = b2[t];
        #pragma unroll
        for (int kk = 0; kk < 16; kk++) {
            float4 wv = w2r[kk];
            f = fmaf(havg_s[4 * kk + 0], wv.x, f);
            f = fmaf(havg_s[4 * kk + 1], wv.y, f);
            f = fmaf(havg_s[4 * kk + 2], wv.z, f);
            f = fmaf(havg_s[4 * kk + 3], wv.w, f);
        }
        out_feat[(long)b * EE + t] = f;
    }
}

extern "C" void kernel_launch(void* const* d_in, const int* in_sizes, int n_in,
                              void* d_out, int out_size) {
    const int*   x  = (const int*)d_in[0];
    const float* w1 = (const float*)d_in[1];
    const float* b1 = (const float*)d_in[2];
    const float* w2 = (const float*)d_in[3];
    const float* b2 = (const float*)d_in[4];
    float* out = (float*)d_out;
    patcher_kernel<<<BB, NT>>>(x, w1, b1, w2, b2, out, out + BB * EE);
}

// round 6
// speedup vs baseline: 2.2038x; 1.0094x over previous
#include <cuda_runtime.h>
#include <stdint.h>

#define BB 256
#define LL 8192
#define EE 64
#define M3 2731            // ceil(L/3) chain nodes (patch starts are multiples of 3)
#define NT 512             // threads per block (one row per block)
#define CH 6               // m-nodes per chunk, 512 chunks: 512*6 = 3072 >= 2731
#define PACKN 3080         // padded packed array (reads up to index 3075)

#define BYTEJ(j) ((int)((bw[(j) >> 2] >> (((j) & 3) * 8)) & 0xFF))

__device__ __forceinline__ unsigned compose4(unsigned e0, unsigned e1, unsigned e2,
                                             unsigned e3, unsigned p) {
    // apply p (earlier map) first, then own map {e0..e3}; value = (count<<2)|exit_off
    unsigned r1 = p & 3u;
    unsigned a   = (r1 & 1u) ? e1 : e0;
    unsigned bb_ = (r1 & 1u) ? e3 : e2;
    unsigned own = (r1 & 2u) ? bb_ : a;
    return own + (p & ~3u);
}

__global__ __launch_bounds__(NT, 2)
void patcher_kernel(const int* __restrict__ x,
                    const float* __restrict__ w1,
                    const float* __restrict__ b1,
                    const float* __restrict__ w2,
                    const float* __restrict__ b2,
                    float* __restrict__ out_feat,   // [B,E]
                    float* __restrict__ out_ent)    // [B,L]
{
    __shared__ uint32_t stage_s[2304];       // 2048 words + bank padding (w + w>>3)
    __shared__ int      packed_s[PACKN];     // (cs3<<1)|bit, sentinels 0 beyond M3
    __shared__ int      hist_s[16 * 64];     // per-warp histograms over q in [0,48]
    __shared__ int      hist_tot_s[52];
    __shared__ unsigned wm_s[64];            // 16 warp maps x 4 entries
    __shared__ unsigned wb0_s[17];           // exclusive warp-base maps at entry 0
    __shared__ unsigned g0_s[NT];            // inclusive composite evaluated at 0
    __shared__ int      warp_sums_s[16];
    __shared__ int      wbase16_s[16];
    __shared__ int      total_sm;
    __shared__ float    clip_mean_s;
    __shared__ int      clip_flag_s;
    __shared__ float    hpart_s[8 * EE];
    __shared__ float    havg_s[EE];

    const int b = blockIdx.x;
    const int t = threadIdx.x;
    const int lane = t & 31;
    const int wid  = t >> 5;                 // 0..15
    const unsigned FULL = 0xffffffffu;
    const int* __restrict__ xrow = x + (long)b * LL;

    // ---- register tables broadcast via shfl (lane c holds entry c) ----
    float fl    = (float)lane;
    float clogv = (lane >= 2) ? fl * log2f(fl) : 0.0f;   // c*log2(c)
    float fl1   = fl + 1.0f;
    float dtabv = fl1 * log2f(fl1) - clogv;              // dlog(c)

    // ---- init smem ----
    hist_s[t] = 0;
    hist_s[t + NT] = 0;
    if (t < PACKN - M3) packed_s[M3 + t] = 0;
    if (t == 0) { clip_flag_s = 0; clip_mean_s = 0.0f; }

    // ---- coalesced gmem load -> bank-padded byte staging ----
    {
        const int4* xv4 = (const int4*)xrow;
        #pragma unroll
        for (int j = 0; j < 4; j++) {
            int w = t + NT * j;
            int4 v = xv4[w];
            uint32_t pk = (unsigned)v.x | ((unsigned)v.y << 8) |
                          ((unsigned)v.z << 16) | ((unsigned)v.w << 24);
            stage_s[w + (w >> 3)] = pk;
        }
    }
    __syncthreads();

    // ---- window words: bw[q] = word 4t-1+q (clamped dup at edges) ----
    unsigned bw[6];
    {
        int w0 = 4 * t - 1; if (w0 < 0) w0 = 0;              // only t==0 clamps
        bw[0] = stage_s[w0 + (w0 >> 3)];
        #pragma unroll
        for (int q = 1; q < 5; q++) {
            int w = 4 * t - 1 + q;                           // always in range
            bw[q] = stage_s[w + (w >> 3)];
        }
        int w5 = 4 * t + 4; if (w5 > 2047) w5 = 2047;        // only t==NT-1 clamps
        bw[5] = stage_s[w5 + (w5 >> 3)];
    }

    // initial histogram: bytes 0..8 (uniform; edge threads self-correct)
    int hp = 0;
    #pragma unroll
    for (int jj = 0; jj <= 8; jj++) hp += 1 << (BYTEJ(jj) * 6);
    float S = 0.0f;
    #pragma unroll
    for (int q = 0; q < 5; q++) {
        int c = (hp >> (6 * q)) & 63;
        S += __shfl_sync(FULL, clogv, c);
    }

    int rr   = t % 3;                    // i0 % 3 (16 == 1 mod 3)
    int mreg = (16 * t + 2) / 3;         // first m with 3m >= 16t
    const int mlo = mreg;
    int run = 0;                         // sum of tokens [16t, i)
    float* erow = out_ent + (long)b * LL + 16 * t;
    float4 ebuf;

    #pragma unroll
    for (int k = 0; k < 16; k++) {
        float ent = 3.16992500144f - S * (1.0f / 9.0f);    // uniform interior
        if      ((k & 3) == 0) ebuf.x = ent;
        else if ((k & 3) == 1) ebuf.y = ent;
        else if ((k & 3) == 2) ebuf.z = ent;
        else {
            ebuf.w = ent;
            *reinterpret_cast<float4*>(erow + (k - 3)) = ebuf;
        }

        if (rr == 0) {
            packed_s[mreg] = (run << 1) | (ent > 1.5f ? 1 : 0);
            mreg++;
        }
        rr = (rr == 2) ? 0 : rr + 1;
        run += BYTEJ(k + 4);             // token i = 16t+k is byte k+4

        if (k < 15) {
            int sh1 = BYTEJ(k) * 6;                       // drop (count >= 1 always)
            int c_out = (hp >> sh1) & 63;
            float dl_out = __shfl_sync(FULL, dtabv, c_out - 1);
            hp -= 1 << sh1;  S -= dl_out;
            int sh2 = BYTEJ(k + 9) * 6;                   // add
            int c_in = (hp >> sh2) & 63;
            float dl_in = __shfl_sync(FULL, dtabv, c_in);
            hp += 1 << sh2;  S += dl_in;
        }
    }
    const int mhi = mreg;

    // ---- edge fixups: recompute 4 clipped-window entropies directly ----
    if (t == 0) {
        int hp2 = 0;
        #pragma unroll
        for (int j = 4; j <= 7; j++) hp2 += 1 << (BYTEJ(j) * 6);   // tokens 0..3
        float ee[4];
        #pragma unroll
        for (int k = 0; k < 4; k++) {
            hp2 += 1 << (BYTEJ(k + 8) * 6);                        // token k+4
            float tot = (float)(k + 5);
            float S2 = 0.0f;
            #pragma unroll
            for (int q = 0; q < 5; q++) {
                float fc = (float)((hp2 >> (6 * q)) & 63);
                S2 += fc * log2f(fmaxf(fc, 1.0f));
            }
            ee[k] = log2f(tot) - S2 / tot;
        }
        float4 ev; ev.x = ee[0]; ev.y = ee[1]; ev.z = ee[2]; ev.w = ee[3];
        *reinterpret_cast<float4*>(erow) = ev;
        packed_s[0] = (packed_s[0] & ~1) | (ee[0] > 1.5f ? 1 : 0);   // m=0 (k=0)
        packed_s[1] = (packed_s[1] & ~1) | (ee[3] > 1.5f ? 1 : 0);   // m=1 (k=3)
    }
    if (t == NT - 1) {
        int hp2 = 0;
        #pragma unroll
        for (int j = 12; j <= 19; j++) hp2 += 1 << (BYTEJ(j) * 6); // tokens 8184..8191
        float ee[4];
        #pragma unroll
        for (int k = 12; k < 16; k++) {
            float tot = (float)(20 - k);
            float S2 = 0.0f;
            #pragma unroll
            for (int q = 0; q < 5; q++) {
                float fc = (float)((hp2 >> (6 * q)) & 63);
                S2 += fc * log2f(fmaxf(fc, 1.0f));
            }
            ee[k - 12] = log2f(tot) - S2 / tot;
            hp2 -= 1 << (BYTEJ(k) * 6);                            // drop leftmost
        }
        float4 ev; ev.x = ee[0]; ev.y = ee[1]; ev.z = ee[2]; ev.w = ee[3];
        *reinterpret_cast<float4*>(erow + 12) = ev;
        packed_s[2730] = (packed_s[2730] & ~1) | (ee[2] > 1.5f ? 1 : 0); // m=2730 (k=14)
    }
    __syncthreads();

    // ================= phase A (reads LSBs only) =============================
    unsigned e0, e1, e2, e3;
    {
        const int mend = CH * (t + 1);
        int mm0 = CH * t + 0, mm1 = CH * t + 1, mm2 = CH * t + 2, mm3 = CH * t + 3;
        int cc0 = 0, cc1 = 0, cc2 = 0, cc3 = 0;
        #pragma unroll
        for (int it = 0; it < CH; it++) {
            int pk0 = packed_s[mm0], pk1 = packed_s[mm1];
            int pk2 = packed_s[mm2], pk3 = packed_s[mm3];
            bool a0 = mm0 < mend, a1 = mm1 < mend, a2 = mm2 < mend, a3 = mm3 < mend;
            cc0 += (a0 && mm0 < M3) ? 1 : 0;
            cc1 += (a1 && mm1 < M3) ? 1 : 0;
            cc2 += (a2 && mm2 < M3) ? 1 : 0;
            cc3 += (a3 && mm3 < M3) ? 1 : 0;
            mm0 += a0 ? ((pk0 & 1) ? 1 : 4) : 0;
            mm1 += a1 ? ((pk1 & 1) ? 1 : 4) : 0;
            mm2 += a2 ? ((pk2 & 1) ? 1 : 4) : 0;
            mm3 += a3 ? ((pk3 & 1) ? 1 : 4) : 0;
        }
        e0 = ((unsigned)cc0 << 2) | (unsigned)(mm0 - mend);
        e1 = ((unsigned)cc1 << 2) | (unsigned)(mm1 - mend);
        e2 = ((unsigned)cc2 << 2) | (unsigned)(mm2 - mend);
        e3 = ((unsigned)cc3 << 2) | (unsigned)(mm3 - mend);
    }

    // ---- merged intra-warp scans: token sums + chain composition ----
    int v = run;
    #pragma unroll
    for (int d = 1; d < 32; d <<= 1) {
        int      nv = __shfl_up_sync(FULL, v, d);
        unsigned p0 = __shfl_up_sync(FULL, e0, d);
        unsigned p1 = __shfl_up_sync(FULL, e1, d);
        unsigned p2 = __shfl_up_sync(FULL, e2, d);
        unsigned p3 = __shfl_up_sync(FULL, e3, d);
        if (lane >= d) {
            v += nv;
            unsigned n0 = compose4(e0, e1, e2, e3, p0);
            unsigned n1 = compose4(e0, e1, e2, e3, p1);
            unsigned n2 = compose4(e0, e1, e2, e3, p2);
            unsigned n3 = compose4(e0, e1, e2, e3, p3);
            e0 = n0; e1 = n1; e2 = n2; e3 = n3;
        }
    }
    int excl = v - run;
    if (lane == 31) {
        warp_sums_s[wid] = v;
        wm_s[wid * 4 + 0] = e0; wm_s[wid * 4 + 1] = e1;
        wm_s[wid * 4 + 2] = e2; wm_s[wid * 4 + 3] = e3;
    }
    __syncthreads();

    // ---- warp 0: inter-warp scans (sums + composition) ----
    if (wid == 0) {
        int ws = (lane < 16) ? warp_sums_s[lane] : 0;
        int vv = ws;
        unsigned f0 = (lane < 16) ? wm_s[lane * 4 + 0] : 0u;
        unsigned f1 = (lane < 16) ? wm_s[lane * 4 + 1] : 1u;
        unsigned f2 = (lane < 16) ? wm_s[lane * 4 + 2] : 2u;
        unsigned f3 = (lane < 16) ? wm_s[lane * 4 + 3] : 3u;
        #pragma unroll
        for (int d = 1; d < 16; d <<= 1) {
            int      nv = __shfl_up_sync(FULL, vv, d);
            unsigned p0 = __shfl_up_sync(FULL, f0, d);
            unsigned p1 = __shfl_up_sync(FULL, f1, d);
            unsigned p2 = __shfl_up_sync(FULL, f2, d);
            unsigned p3 = __shfl_up_sync(FULL, f3, d);
            if (lane >= d && lane < 16) {
                vv += nv;
                unsigned n0 = compose4(f0, f1, f2, f3, p0);
                unsigned n1 = compose4(f0, f1, f2, f3, p1);
                unsigned n2 = compose4(f0, f1, f2, f3, p2);
                unsigned n3 = compose4(f0, f1, f2, f3, p3);
                f0 = n0; f1 = n1; f2 = n2; f3 = n3;
            }
        }
        if (lane < 16) { wbase16_s[lane] = vv - ws; wb0_s[lane + 1] = f0; }
        if (lane == 15) total_sm = vv;
        if (lane == 31) wb0_s[0] = 0u;
    }
    __syncthreads();

    // ---- inclusive composite at entry 0 + cs3 base fixup ----
    g0_s[t] = compose4(e0, e1, e2, e3, wb0_s[wid]);
    {
        int base2 = (wbase16_s[wid] + excl) << 1;
        for (int m2 = mlo; m2 < mhi; m2++) packed_s[m2] += base2;
    }
    __syncthreads();

    // ================= phase B: walk real path, histogram patch sums =========
    {
        unsigned ge = (t == 0) ? 0u : g0_s[t - 1];
        int m = CH * t + (int)(ge & 3u);
        const int mend = CH * (t + 1);
        const int totalv = total_sm;
        int* hw = &hist_s[wid * 64];
        while (m < mend) {
            int pk  = packed_s[m];
            int bit = pk & 1;
            int s   = bit ? 1 : 4;
            if (m < M3) {
                if (m + s <= M3 - 1) {
                    int sum = (packed_s[m + s] >> 1) - (pk >> 1);
                    int q = bit ? (sum << 2) : sum;    // mean = q/12
                    atomicAdd(&hw[q], 1);
                } else {
                    clip_mean_s = (float)(totalv - (pk >> 1)) / (float)(LL - 3 * m);
                    clip_flag_s = 1;
                }
            }
            m += s;
        }
    }
    __syncthreads();

    // ---- reduce per-warp histograms ----
    if (t < 49) {
        int s = 0;
        #pragma unroll
        for (int w = 0; w < 16; w++) s += hist_s[w * 64 + t];
        hist_tot_s[t] = s;
    }
    __syncthreads();

    // ================= MLP: hist-weighted relu accumulate ====================
    {
        int e = t & 63;
        int g = t >> 6;                  // 0..7
        float w1e = w1[e];
        float b1e = b1[e];
        float acc = 0.0f;
        int q0 = g * 7;
        int q1 = q0 + 7; if (q1 > 49) q1 = 49;
        for (int q = q0; q < q1; q++) {
            int c = hist_tot_s[q];
            if (c) acc += (float)c * fmaxf(fmaf((float)q * (1.0f / 12.0f), w1e, b1e), 0.0f);
        }
        if (g == 0 && clip_flag_s)
            acc += fmaxf(fmaf(clip_mean_s, w1e, b1e), 0.0f);
        hpart_s[g * EE + e] = acc;
    }
    __syncthreads();

    if (t < EE) {
        float npf = (float)(g0_s[NT - 1] >> 2);
        float s = 0.0f;
        #pragma unroll
        for (int g = 0; g < 8; g++) s += hpart_s[g * EE + t];
        havg_s[t] = s / npf;
    }
    __syncthreads();

    // ---- final 64x64 GEMV ----
    if (t < EE) {
        const float4* w2r = reinterpret_cast<const float4*>(w2 + t * EE);
        float f = b2[t];
        #pragma unroll
        for (int kk = 0; kk < 16; kk++) {
            float4 wv = w2r[kk];
            f = fmaf(havg_s[4 * kk + 0], wv.x, f);
            f = fmaf(havg_s[4 * kk + 1], wv.y, f);
            f = fmaf(havg_s[4 * kk + 2], wv.z, f);
            f = fmaf(havg_s[4 * kk + 3], wv.w, f);
        }
        out_feat[(long)b * EE + t] = f;
    }
}

extern "C" void kernel_launch(void* const* d_in, const int* in_sizes, int n_in,
                              void* d_out, int out_size) {
    const int*   x  = (const int*)d_in[0];
    const float* w1 = (const float*)d_in[1];
    const float* b1 = (const float*)d_in[2];
    const float* w2 = (const float*)d_in[3];
    const float* b2 = (const float*)d_in[4];
    float* out = (float*)d_out;
    patcher_kernel<<<BB, NT>>>(x, w1, b1, w2, b2, out, out + BB * EE);
}